// round 15
// baseline (speedup 1.0000x reference)
#include <cuda_runtime.h>
#include <cuda_fp16.h>
#include <cstdint>

#define NNODES 10000
#define NEDGES 160000
#define HID    512
#define NOUT   16

// ---------------- device scratch ----------------
__device__ __half g_hq[NNODES * HID];        // GEMM output fp16 (both layers)
__device__ __half g_xq[NNODES * HID];        // x fp16
__device__ __half g_aq[NNODES * HID];        // agg1 out fp16 / agg2 out fp16 (reused)
__device__ __half g_w1[HID * HID];           // W1^T fp16
__device__ __half g_w2[HID * HID];           // W2^T fp16
__device__ float g_dinv[NNODES];
__device__ int   g_degcnt[NNODES];
__device__ int   g_fill[NNODES];
__device__ int   g_rowstart[NNODES];
__device__ int   g_total;
__device__ int   g_srcv[NEDGES];
__device__ int   g_dsttmp[NEDGES];
__device__ int   g_adjout[NEDGES];

__device__ __forceinline__ uint32_t smem_to_u32(const void* p) {
    uint32_t a;
    asm("{ .reg .u64 t; cvta.to.shared.u64 t, %1; cvt.u32.u64 %0, t; }" : "=r"(a) : "l"(p));
    return a;
}

__device__ __forceinline__ void cp_async16(uint32_t dst, const void* src, bool pred) {
    int sz = pred ? 16 : 0;
    asm volatile("cp.async.cg.shared.global [%0], [%1], 16, %2;\n"
                 :: "r"(dst), "l"(src), "r"(sz));
}
__device__ __forceinline__ void cp_commit() {
    asm volatile("cp.async.commit_group;\n" ::: "memory");
}
template <int N>
__device__ __forceinline__ void cp_wait() {
    asm volatile("cp.async.wait_group %0;\n" :: "n"(N) : "memory");
}

__device__ __forceinline__ void ldsm4(uint32_t addr, uint32_t r[4]) {
    asm volatile("ldmatrix.sync.aligned.m8n8.x4.shared.b16 {%0,%1,%2,%3}, [%4];"
                 : "=r"(r[0]), "=r"(r[1]), "=r"(r[2]), "=r"(r[3]) : "r"(addr));
}

__device__ __forceinline__ void mma_f16(float acc[4], const uint32_t a[4],
                                        uint32_t b0, uint32_t b1) {
    asm volatile(
        "mma.sync.aligned.m16n8k16.row.col.f32.f16.f16.f32 "
        "{%0,%1,%2,%3}, {%4,%5,%6,%7}, {%8,%9}, {%0,%1,%2,%3};"
        : "+f"(acc[0]), "+f"(acc[1]), "+f"(acc[2]), "+f"(acc[3])
        : "r"(a[0]), "r"(a[1]), "r"(a[2]), "r"(a[3]), "r"(b0), "r"(b1));
}

// ---------------- launch 0: fused prep (xconv | wconv | convert) -------------
__global__ __launch_bounds__(256) void prep_kernel(const float* __restrict__ x,
                                                   const float* __restrict__ W1,
                                                   const float* __restrict__ W2,
                                                   const void* __restrict__ ei,
                                                   int E, int n4, int XB) {
    int b = blockIdx.x;
    int t = threadIdx.x;
    if (b < XB) {
        int i = b * 256 + t;
        if (i < NNODES) { g_degcnt[i] = 0; g_fill[i] = 0; }
        if (i == 0) g_total = 0;
        if (i >= n4) return;
        float4 v = ((const float4*)x)[i];
        ((__half2*)g_xq)[i * 2]     = __halves2half2(__float2half(v.x), __float2half(v.y));
        ((__half2*)g_xq)[i * 2 + 1] = __halves2half2(__float2half(v.z), __float2half(v.w));
    } else if (b < XB + 512) {
        __shared__ float tile[32][33];
        int wb = b - XB;
        int z = wb >> 8;
        int t16 = wb & 255;
        const float* W = z ? W2 : W1;
        __half* Th = z ? g_w2 : g_w1;
        int n0 = (t16 & 15) * 32, k0 = (t16 >> 4) * 32;
#pragma unroll
        for (int j = 0; j < 4; j++) {
            int idx = t + j * 256;
            int r = idx >> 5, c = idx & 31;
            tile[r][c] = W[(size_t)(k0 + r) * HID + n0 + c];
        }
        __syncthreads();
#pragma unroll
        for (int j = 0; j < 4; j++) {
            int idx = t + j * 256;
            int r = idx >> 5, c = idx & 31;
            Th[(size_t)(n0 + r) * HID + k0 + c] = __float2half(tile[c][r]);
        }
    } else {
        __shared__ int s_is64;
        if (t == 0) {
            const unsigned int* p = (const unsigned int*)ei;
            int is64 = 1;
            for (int i = 1; i < 128; i += 2)
                if (p[i] != 0u) { is64 = 0; break; }
            s_is64 = is64;
        }
        __syncthreads();
        int e = (b - XB - 512) * 256 + t;
        if (e >= E) return;
        int s, d;
        if (s_is64) {
            const long long* p = (const long long*)ei;
            s = (int)p[e]; d = (int)p[E + e];
        } else {
            const int* p = (const int*)ei;
            s = p[e]; d = p[E + e];
        }
        g_srcv[e] = s;
        g_dsttmp[e] = d;
        atomicAdd(&g_degcnt[d], 1);
    }
}

// ---------------- row starts (unordered CSR) + dinv ----------------
__global__ void rowstart_kernel(int M) {
    int i = blockIdx.x * blockDim.x + threadIdx.x;
    if (i >= M) return;
    int d = g_degcnt[i];
    g_dinv[i] = rsqrtf((float)d + 1.0f);
    g_rowstart[i] = atomicAdd(&g_total, d);
}

// ---------------- adjacency fill ----------------
__global__ void fill_kernel(int E) {
    int e = blockIdx.x * blockDim.x + threadIdx.x;
    if (e >= E) return;
    int d = g_dsttmp[e];
    int s = g_srcv[e];
    int p = atomicAdd(&g_fill[d], 1);
    g_adjout[g_rowstart[d] + p] = s;
}

// ---------------- 3-stage fp16 GEMM, 96x128 tile: Cq = A @ B^T (fp16 out) ----
// Grid (4, ceil(M/96)=105) = 420 tiles -> 2.84 tiles/SM-slot, max 3 (5.7% imbal).
// 384 threads = 12 warps (3 x 4), warp tile 32x32, 2 CTAs/SM.
#define KC      32
#define NC      (HID / KC)              // 16 chunks
#define TSTRIDE 40                      // 32 data + 8 pad halves
#define MT      96                      // M tile
#define A_TILEB (MT * TSTRIDE * 2)      // 7680 B
#define B_TILEB (128 * TSTRIDE * 2)     // 10240 B
#define STAGEB  (A_TILEB + B_TILEB)     // 17920 B
#define NSTAGE  3
#define NQUADS  ((MT + 128) * 4)        // 896 quads per stage fill

__global__ __launch_bounds__(384, 2) void gemm_mma(const __half* __restrict__ Ag,
                                                   const __half* __restrict__ Bg,
                                                   __half* __restrict__ Cq, int M) {
    extern __shared__ char dynsm[];
    uint32_t sbase = smem_to_u32(dynsm);

    int tid = threadIdx.x;
    int wid = tid >> 5, lane = tid & 31;
    int bm = blockIdx.y * MT, bn = blockIdx.x * 128;
    int wm = (wid >> 2) * 32;     // 3 warp rows
    int wn = (wid & 3) * 32;      // 4 warp cols

    float acc[2][4][4];
#pragma unroll
    for (int i = 0; i < 2; i++)
#pragma unroll
        for (int n = 0; n < 4; n++)
#pragma unroll
            for (int q = 0; q < 4; q++) acc[i][n][q] = 0.0f;

    int a_row = (lane & 7) + ((lane >> 3) & 1) * 8;
    int a_col = (lane >> 4) * 8;
    int b_row = (lane & 7) + (lane >> 4) * 8;
    int b_col = ((lane >> 3) & 1) * 8;

    auto issue = [&](int c, int s) {
        uint32_t st = sbase + s * STAGEB;
        for (int i = tid; i < NQUADS; i += 384) {
            if (i < MT * 4) {
                int row = i >> 2, q = i & 3;
                bool v = (bm + row) < M;
                cp_async16(st + (uint32_t)(row * TSTRIDE) * 2 + q * 16,
                           Ag + (size_t)(bm + row) * HID + c * KC + q * 8, v);
            } else {
                int j = i - MT * 4;
                int row = j >> 2, q = j & 3;
                cp_async16(st + A_TILEB + (uint32_t)(row * TSTRIDE) * 2 + q * 16,
                           Bg + (size_t)(bn + row) * HID + c * KC + q * 8, true);
            }
        }
        cp_commit();
    };

    issue(0, 0);
    issue(1, 1);

    for (int c = 0; c < NC; c++) {
        int s = c % NSTAGE;
        if (c + 2 < NC) issue(c + 2, (c + 2) % NSTAGE);
        cp_wait<2>();
        __syncthreads();

        uint32_t st = sbase + s * STAGEB;
        uint32_t bA = st, bB = st + A_TILEB;

#pragma unroll
        for (int ks = 0; ks < 2; ks++) {
            int k0 = ks * 16;
            uint32_t af[2][4], bf[2][4];
#pragma unroll
            for (int i = 0; i < 2; i++) {
                uint32_t off = ((uint32_t)(wm + i * 16 + a_row) * TSTRIDE + k0 + a_col) * 2;
                ldsm4(bA + off, af[i]);
            }
#pragma unroll
            for (int j = 0; j < 2; j++) {
                uint32_t off = ((uint32_t)(wn + j * 16 + b_row) * TSTRIDE + k0 + b_col) * 2;
                ldsm4(bB + off, bf[j]);
            }

#pragma unroll
            for (int i = 0; i < 2; i++) {
#pragma unroll
                for (int n = 0; n < 4; n++) {
                    uint32_t h0 = bf[n >> 1][(n & 1) * 2];
                    uint32_t h1 = bf[n >> 1][(n & 1) * 2 + 1];
                    mma_f16(acc[i][n], af[i], h0, h1);
                }
            }
        }
        __syncthreads();
    }

#pragma unroll
    for (int i = 0; i < 2; i++) {
#pragma unroll
        for (int n = 0; n < 4; n++) {
            int r0 = bm + wm + i * 16 + (lane >> 2);
            int col = bn + wn + n * 8 + (lane & 3) * 2;
            int r1 = r0 + 8;
            if (r0 < M)
                *(__half2*)&Cq[(size_t)r0 * HID + col] =
                    __halves2half2(__float2half(acc[i][n][0]), __float2half(acc[i][n][1]));
            if (r1 < M)
                *(__half2*)&Cq[(size_t)r1 * HID + col] =
                    __halves2half2(__float2half(acc[i][n][2]), __float2half(acc[i][n][3]));
        }
    }
}

// ---------------- agg: fp16 gather + bias + relu -> fp16 out ----------------
__global__ __launch_bounds__(128) void agg_kernel(const __half* __restrict__ h,
                                                  const float* __restrict__ bias,
                                                  __half* __restrict__ oq) {
    int v = blockIdx.x;
    int t = threadIdx.x;
    const uint2* h2 = (const uint2*)h;
    float dv = g_dinv[v];
    int beg = g_rowstart[v], end = beg + g_degcnt[v];

    uint2 raw = h2[(size_t)v * (HID / 4) + t];
    __half2 p0 = *(__half2*)&raw.x, p1 = *(__half2*)&raw.y;
    float sl = dv * dv;
    float4 acc;
    acc.x = sl * __low2float(p0);  acc.y = sl * __high2float(p0);
    acc.z = sl * __low2float(p1);  acc.w = sl * __high2float(p1);
    for (int j = beg; j < end; j++) {
        int s = g_adjout[j];
        float nm = dv * g_dinv[s];
        uint2 r = h2[(size_t)s * (HID / 4) + t];
        __half2 q0 = *(__half2*)&r.x, q1 = *(__half2*)&r.y;
        acc.x += nm * __low2float(q0);  acc.y += nm * __high2float(q0);
        acc.z += nm * __low2float(q1);  acc.w += nm * __high2float(q1);
    }
    float4 bb = *(const float4*)(bias + t * 4);
    acc.x = fmaxf(acc.x + bb.x, 0.0f);
    acc.y = fmaxf(acc.y + bb.y, 0.0f);
    acc.z = fmaxf(acc.z + bb.z, 0.0f);
    acc.w = fmaxf(acc.w + bb.w, 0.0f);

    size_t o2 = (size_t)v * (HID / 2) + t * 2;
    ((__half2*)oq)[o2]     = __halves2half2(__float2half(acc.x), __float2half(acc.y));
    ((__half2*)oq)[o2 + 1] = __halves2half2(__float2half(acc.z), __float2half(acc.w));
}

// ---------------- final logits (fp16 h, fp16 Ws, fp32 accumulate) ------------
__global__ __launch_bounds__(256) void final_gemm(const __half* __restrict__ h,
                                                  const float* __restrict__ Wl,
                                                  const float* __restrict__ bl,
                                                  float* __restrict__ out, int M) {
    __shared__ __half Ws[HID][NOUT];
    int tx = threadIdx.x;
    int ty = threadIdx.y;
    int tid = ty * 16 + tx;
    for (int i = tid; i < HID * NOUT; i += 256)
        Ws[i / NOUT][i % NOUT] = __float2half(Wl[i]);
    __syncthreads();

    int r = blockIdx.x * 16 + ty;
    if (r >= M) return;
    const __half* hr = h + (size_t)r * HID;
    float acc = bl[tx];
#pragma unroll 8
    for (int k = 0; k < HID; k++)
        acc += __half2float(hr[k]) * __half2float(Ws[k][tx]);
    out[(size_t)r * NOUT + tx] = acc;
}

// ---------------- host launch ----------------
extern "C" void kernel_launch(void* const* d_in, const int* in_sizes, int n_in,
                              void* d_out, int out_size) {
    const float* x  = (const float*)d_in[0];
    const void*  ei = d_in[1];
    const float* W1 = (const float*)d_in[2];
    const float* b1 = (const float*)d_in[3];
    const float* W2 = (const float*)d_in[4];
    const float* b2 = (const float*)d_in[5];
    const float* Wl = (const float*)d_in[6];
    const float* bl = (const float*)d_in[7];
    float* out = (float*)d_out;

    int M = in_sizes[0] / HID;
    int E = in_sizes[1] / 2;

    void *p_hq, *p_xq, *p_aq, *p_w1, *p_w2;
    cudaGetSymbolAddress(&p_hq, g_hq);
    cudaGetSymbolAddress(&p_xq, g_xq);
    cudaGetSymbolAddress(&p_aq, g_aq);
    cudaGetSymbolAddress(&p_w1, g_w1);
    cudaGetSymbolAddress(&p_w2, g_w2);

    const int GEMM_SMEM = NSTAGE * STAGEB;   // 53760 bytes
    cudaFuncSetAttribute(gemm_mma, cudaFuncAttributeMaxDynamicSharedMemorySize, GEMM_SMEM);

    int n4 = M * HID / 4;
    int XB = (n4 + 255) / 256;
    int EB = (E + 255) / 256;
    dim3 ggrid(HID / 128, (M + MT - 1) / MT);

    // launch 0: fused prep (xconv | wconv | edge convert)
    prep_kernel<<<XB + 512 + EB, 256>>>(x, W1, W2, ei, E, n4, XB);
    // launch 1: row starts + dinv
    rowstart_kernel<<<(M + 255) / 256, 256>>>(M);
    // launch 2: adjacency fill
    fill_kernel<<<(E + 255) / 256, 256>>>(E);
    // launch 3: layer-1 GEMM (fp16 out)  <-- ncu snapshot lands here
    gemm_mma<<<ggrid, 384, GEMM_SMEM>>>((const __half*)p_xq, (const __half*)p_w1,
                                        (__half*)p_hq, M);
    // launch 4: agg1 (fp16 gather -> fp16)
    agg_kernel<<<M, 128>>>((const __half*)p_hq, b1, (__half*)p_aq);
    // launch 5: layer-2 GEMM (fp16 out)
    gemm_mma<<<ggrid, 384, GEMM_SMEM>>>((const __half*)p_aq, (const __half*)p_w2,
                                        (__half*)p_hq, M);
    // launch 6: agg2 (fp16 gather -> fp16)
    agg_kernel<<<M, 128>>>((const __half*)p_hq, b2, (__half*)p_aq);
    // launch 7: logits (fp16 inputs, fp32 out)
    final_gemm<<<(M + 15) / 16, dim3(16, 16)>>>((const __half*)p_aq, Wl, bl, out, M);
}

// round 17
// speedup vs baseline: 1.1282x; 1.1282x over previous
#include <cuda_runtime.h>
#include <cuda_fp16.h>
#include <cstdint>

#define NNODES 10000
#define NEDGES 160000
#define HID    512
#define NOUT   16

// ---------------- device scratch ----------------
__device__ __half g_hq[NNODES * HID];        // GEMM output fp16 (both layers)
__device__ __half g_xq[NNODES * HID];        // x fp16
__device__ __half g_aq[NNODES * HID];        // agg1 out fp16 / agg2 out fp16 (reused)
__device__ __half g_w1[HID * HID];           // W1^T fp16
__device__ __half g_w2[HID * HID];           // W2^T fp16
__device__ float g_dinv[NNODES];
__device__ int   g_degcnt[NNODES];
__device__ int   g_fill[NNODES];
__device__ int   g_rowstart[NNODES];
__device__ int   g_total;
__device__ int   g_srcv[NEDGES];
__device__ int   g_dsttmp[NEDGES];
__device__ int   g_adjout[NEDGES];

__device__ __forceinline__ uint32_t smem_to_u32(const void* p) {
    uint32_t a;
    asm("{ .reg .u64 t; cvta.to.shared.u64 t, %1; cvt.u32.u64 %0, t; }" : "=r"(a) : "l"(p));
    return a;
}

__device__ __forceinline__ void cp_async16(uint32_t dst, const void* src, bool pred) {
    int sz = pred ? 16 : 0;
    asm volatile("cp.async.cg.shared.global [%0], [%1], 16, %2;\n"
                 :: "r"(dst), "l"(src), "r"(sz));
}
__device__ __forceinline__ void cp_commit() {
    asm volatile("cp.async.commit_group;\n" ::: "memory");
}
template <int N>
__device__ __forceinline__ void cp_wait() {
    asm volatile("cp.async.wait_group %0;\n" :: "n"(N) : "memory");
}

__device__ __forceinline__ void ldsm4(uint32_t addr, uint32_t r[4]) {
    asm volatile("ldmatrix.sync.aligned.m8n8.x4.shared.b16 {%0,%1,%2,%3}, [%4];"
                 : "=r"(r[0]), "=r"(r[1]), "=r"(r[2]), "=r"(r[3]) : "r"(addr));
}

__device__ __forceinline__ void mma_f16(float acc[4], const uint32_t a[4],
                                        uint32_t b0, uint32_t b1) {
    asm volatile(
        "mma.sync.aligned.m16n8k16.row.col.f32.f16.f16.f32 "
        "{%0,%1,%2,%3}, {%4,%5,%6,%7}, {%8,%9}, {%0,%1,%2,%3};"
        : "+f"(acc[0]), "+f"(acc[1]), "+f"(acc[2]), "+f"(acc[3])
        : "r"(a[0]), "r"(a[1]), "r"(a[2]), "r"(a[3]), "r"(b0), "r"(b1));
}

// ---------------- launch 0: fused prep (xconv | wconv | convert) -------------
__global__ __launch_bounds__(256) void prep_kernel(const float* __restrict__ x,
                                                   const float* __restrict__ W1,
                                                   const float* __restrict__ W2,
                                                   const void* __restrict__ ei,
                                                   int E, int n4, int XB) {
    int b = blockIdx.x;
    int t = threadIdx.x;
    if (b < XB) {
        int i = b * 256 + t;
        if (i < NNODES) { g_degcnt[i] = 0; g_fill[i] = 0; }
        if (i == 0) g_total = 0;
        if (i >= n4) return;
        float4 v = ((const float4*)x)[i];
        ((__half2*)g_xq)[i * 2]     = __halves2half2(__float2half(v.x), __float2half(v.y));
        ((__half2*)g_xq)[i * 2 + 1] = __halves2half2(__float2half(v.z), __float2half(v.w));
    } else if (b < XB + 512) {
        __shared__ float tile[32][33];
        int wb = b - XB;
        int z = wb >> 8;
        int t16 = wb & 255;
        const float* W = z ? W2 : W1;
        __half* Th = z ? g_w2 : g_w1;
        int n0 = (t16 & 15) * 32, k0 = (t16 >> 4) * 32;
#pragma unroll
        for (int j = 0; j < 4; j++) {
            int idx = t + j * 256;
            int r = idx >> 5, c = idx & 31;
            tile[r][c] = W[(size_t)(k0 + r) * HID + n0 + c];
        }
        __syncthreads();
#pragma unroll
        for (int j = 0; j < 4; j++) {
            int idx = t + j * 256;
            int r = idx >> 5, c = idx & 31;
            Th[(size_t)(n0 + r) * HID + k0 + c] = __float2half(tile[c][r]);
        }
    } else {
        // edge convert + degree count; parallel is64 probe (one load latency,
        // not a serial 64-load chain in thread 0)
        __shared__ int s_nz;
        if (t == 0) s_nz = 0;
        __syncthreads();
        if (t < 64) {
            unsigned int w = ((const unsigned int*)ei)[2 * t + 1];
            if (w != 0u) atomicOr(&s_nz, 1);
        }
        __syncthreads();
        int is64 = (s_nz == 0);
        int e = (b - XB - 512) * 256 + t;
        if (e >= E) return;
        int s, d;
        if (is64) {
            const long long* p = (const long long*)ei;
            s = (int)p[e]; d = (int)p[E + e];
        } else {
            const int* p = (const int*)ei;
            s = p[e]; d = p[E + e];
        }
        g_srcv[e] = s;
        g_dsttmp[e] = d;
        atomicAdd(&g_degcnt[d], 1);
    }
}

// ---------------- row starts (unordered CSR) + dinv ----------------
__global__ void rowstart_kernel(int M) {
    int i = blockIdx.x * blockDim.x + threadIdx.x;
    if (i >= M) return;
    int d = g_degcnt[i];
    g_dinv[i] = rsqrtf((float)d + 1.0f);
    g_rowstart[i] = atomicAdd(&g_total, d);
}

// ---------------- adjacency fill ----------------
__global__ void fill_kernel(int E) {
    int e = blockIdx.x * blockDim.x + threadIdx.x;
    if (e >= E) return;
    int d = g_dsttmp[e];
    int s = g_srcv[e];
    int p = atomicAdd(&g_fill[d], 1);
    g_adjout[g_rowstart[d] + p] = s;
}

// ---------------- 3-stage fp16 GEMM (R14 config): Cq = A @ B^T ---------------
#define KC      32
#define NC      (HID / KC)
#define TSTRIDE 40
#define TILEB   (128 * TSTRIDE * 2)    // 10240 B
#define STAGEB  (2 * TILEB)
#define NSTAGE  3

__global__ __launch_bounds__(512, 2) void gemm_mma(const __half* __restrict__ Ag,
                                                   const __half* __restrict__ Bg,
                                                   __half* __restrict__ Cq, int M) {
    extern __shared__ char dynsm[];
    uint32_t sbase = smem_to_u32(dynsm);

    int tid = threadIdx.x;
    int wid = tid >> 5, lane = tid & 31;
    int bm = blockIdx.y * 128, bn = blockIdx.x * 128;
    int wm = (wid >> 2) * 32;
    int wn = (wid & 3) * 32;

    float acc[2][4][4];
#pragma unroll
    for (int i = 0; i < 2; i++)
#pragma unroll
        for (int n = 0; n < 4; n++)
#pragma unroll
            for (int q = 0; q < 4; q++) acc[i][n][q] = 0.0f;

    int a_row = (lane & 7) + ((lane >> 3) & 1) * 8;
    int a_col = (lane >> 4) * 8;
    int b_row = (lane & 7) + (lane >> 4) * 8;
    int b_col = ((lane >> 3) & 1) * 8;

    int row0 = tid >> 2, q0 = tid & 3;
    bool avalid = (bm + row0) < M;

    auto issue = [&](int c, int s) {
        uint32_t st = sbase + s * STAGEB;
        size_t gA = (size_t)(bm + row0) * HID + c * KC + q0 * 8;
        size_t gB = (size_t)(bn + row0) * HID + c * KC + q0 * 8;
        uint32_t dq = (uint32_t)(row0 * TSTRIDE) * 2 + q0 * 16;
        cp_async16(st + dq, Ag + gA, avalid);
        cp_async16(st + TILEB + dq, Bg + gB, true);
        cp_commit();
    };

    issue(0, 0);
    issue(1, 1);

    for (int c = 0; c < NC; c++) {
        int s = c % NSTAGE;
        if (c + 2 < NC) issue(c + 2, (c + 2) % NSTAGE);
        cp_wait<2>();
        __syncthreads();

        uint32_t st = sbase + s * STAGEB;
        uint32_t bA = st, bB = st + TILEB;

#pragma unroll
        for (int ks = 0; ks < 2; ks++) {
            int k0 = ks * 16;
            uint32_t af[2][4], bf[2][4];
#pragma unroll
            for (int i = 0; i < 2; i++) {
                uint32_t off = ((uint32_t)(wm + i * 16 + a_row) * TSTRIDE + k0 + a_col) * 2;
                ldsm4(bA + off, af[i]);
            }
#pragma unroll
            for (int j = 0; j < 2; j++) {
                uint32_t off = ((uint32_t)(wn + j * 16 + b_row) * TSTRIDE + k0 + b_col) * 2;
                ldsm4(bB + off, bf[j]);
            }

#pragma unroll
            for (int i = 0; i < 2; i++) {
#pragma unroll
                for (int n = 0; n < 4; n++) {
                    uint32_t h0 = bf[n >> 1][(n & 1) * 2];
                    uint32_t h1 = bf[n >> 1][(n & 1) * 2 + 1];
                    mma_f16(acc[i][n], af[i], h0, h1);
                }
            }
        }
        __syncthreads();
    }

#pragma unroll
    for (int i = 0; i < 2; i++) {
#pragma unroll
        for (int n = 0; n < 4; n++) {
            int r0 = bm + wm + i * 16 + (lane >> 2);
            int col = bn + wn + n * 8 + (lane & 3) * 2;
            int r1 = r0 + 8;
            if (r0 < M)
                *(__half2*)&Cq[(size_t)r0 * HID + col] =
                    __halves2half2(__float2half(acc[i][n][0]), __float2half(acc[i][n][1]));
            if (r1 < M)
                *(__half2*)&Cq[(size_t)r1 * HID + col] =
                    __halves2half2(__float2half(acc[i][n][2]), __float2half(acc[i][n][3]));
        }
    }
}

// ---------------- agg: fp16 gather + bias + relu -> fp16 out ----------------
__global__ __launch_bounds__(128) void agg_kernel(const __half* __restrict__ h,
                                                  const float* __restrict__ bias,
                                                  __half* __restrict__ oq) {
    int v = blockIdx.x;
    int t = threadIdx.x;
    const uint2* h2 = (const uint2*)h;
    float dv = g_dinv[v];
    int beg = g_rowstart[v], end = beg + g_degcnt[v];

    uint2 raw = h2[(size_t)v * (HID / 4) + t];
    __half2 p0 = *(__half2*)&raw.x, p1 = *(__half2*)&raw.y;
    float sl = dv * dv;
    float4 acc;
    acc.x = sl * __low2float(p0);  acc.y = sl * __high2float(p0);
    acc.z = sl * __low2float(p1);  acc.w = sl * __high2float(p1);
    for (int j = beg; j < end; j++) {
        int s = g_adjout[j];
        float nm = dv * g_dinv[s];
        uint2 r = h2[(size_t)s * (HID / 4) + t];
        __half2 q0 = *(__half2*)&r.x, q1 = *(__half2*)&r.y;
        acc.x += nm * __low2float(q0);  acc.y += nm * __high2float(q0);
        acc.z += nm * __low2float(q1);  acc.w += nm * __high2float(q1);
    }
    float4 bb = *(const float4*)(bias + t * 4);
    acc.x = fmaxf(acc.x + bb.x, 0.0f);
    acc.y = fmaxf(acc.y + bb.y, 0.0f);
    acc.z = fmaxf(acc.z + bb.z, 0.0f);
    acc.w = fmaxf(acc.w + bb.w, 0.0f);

    size_t o2 = (size_t)v * (HID / 2) + t * 2;
    ((__half2*)oq)[o2]     = __halves2half2(__float2half(acc.x), __float2half(acc.y));
    ((__half2*)oq)[o2 + 1] = __halves2half2(__float2half(acc.z), __float2half(acc.w));
}

// ---------------- final logits: smem-staged, vectorized --------------------
// Block: 256 threads (tx=class 0..15, ty=row 0..15). Stage 16 rows of h and
// all of Wl (fp16) in smem with vector loads, then half2 inner loop.
__global__ __launch_bounds__(256) void final_gemm(const __half* __restrict__ h,
                                                  const float* __restrict__ Wl,
                                                  const float* __restrict__ bl,
                                                  float* __restrict__ out, int M) {
    __shared__ __half Ws[HID][NOUT];        // 16 KB
    __shared__ __half Hs[16][HID];          // 16 KB
    int tx = threadIdx.x;
    int ty = threadIdx.y;
    int tid = ty * 16 + tx;
    int rbase = blockIdx.x * 16;

    // stage Wl (fp32 -> fp16), coalesced
    for (int i = tid; i < HID * NOUT; i += 256)
        Ws[i / NOUT][i % NOUT] = __float2half(Wl[i]);
    // stage 16 rows of h: 1024 16B quads, 4 per thread
#pragma unroll
    for (int j = 0; j < 4; j++) {
        int idx = tid + j * 256;          // 0..1023
        int row = idx >> 6;               // 64 quads per row
        int q = idx & 63;
        int gr = rbase + row;
        uint4 val = make_uint4(0, 0, 0, 0);
        if (gr < M) val = ((const uint4*)(h + (size_t)gr * HID))[q];
        *(uint4*)&Hs[row][q * 8] = val;
    }
    __syncthreads();

    int r = rbase + ty;
    if (r >= M) return;
    float acc = bl[tx];
    const __half2* hrow = (const __half2*)Hs[ty];
#pragma unroll 8
    for (int k2 = 0; k2 < HID / 2; k2++) {
        __half2 hp = hrow[k2];
        acc += __low2float(hp) * __half2float(Ws[k2 * 2][tx]);
        acc += __high2float(hp) * __half2float(Ws[k2 * 2 + 1][tx]);
    }
    out[(size_t)r * NOUT + tx] = acc;
}

// ---------------- host launch (single stream) ----------------
extern "C" void kernel_launch(void* const* d_in, const int* in_sizes, int n_in,
                              void* d_out, int out_size) {
    const float* x  = (const float*)d_in[0];
    const void*  ei = d_in[1];
    const float* W1 = (const float*)d_in[2];
    const float* b1 = (const float*)d_in[3];
    const float* W2 = (const float*)d_in[4];
    const float* b2 = (const float*)d_in[5];
    const float* Wl = (const float*)d_in[6];
    const float* bl = (const float*)d_in[7];
    float* out = (float*)d_out;

    int M = in_sizes[0] / HID;
    int E = in_sizes[1] / 2;

    void *p_hq, *p_xq, *p_aq, *p_w1, *p_w2;
    cudaGetSymbolAddress(&p_hq, g_hq);
    cudaGetSymbolAddress(&p_xq, g_xq);
    cudaGetSymbolAddress(&p_aq, g_aq);
    cudaGetSymbolAddress(&p_w1, g_w1);
    cudaGetSymbolAddress(&p_w2, g_w2);

    const int GEMM_SMEM = NSTAGE * STAGEB;   // 61440 bytes
    cudaFuncSetAttribute(gemm_mma, cudaFuncAttributeMaxDynamicSharedMemorySize, GEMM_SMEM);

    int n4 = M * HID / 4;
    int XB = (n4 + 255) / 256;
    int EB = (E + 255) / 256;
    dim3 ggrid(HID / 128, (M + 127) / 128);

    // launch 0: fused prep (xconv | wconv | edge convert w/ parallel is64)
    prep_kernel<<<XB + 512 + EB, 256>>>(x, W1, W2, ei, E, n4, XB);
    // launch 1: row starts + dinv
    rowstart_kernel<<<(M + 255) / 256, 256>>>(M);
    // launch 2: adjacency fill
    fill_kernel<<<(E + 255) / 256, 256>>>(E);
    // launch 3: layer-1 GEMM (fp16 out)  <-- ncu snapshot lands here
    gemm_mma<<<ggrid, 512, GEMM_SMEM>>>((const __half*)p_xq, (const __half*)p_w1,
                                        (__half*)p_hq, M);
    // launch 4: agg1 (fp16 gather -> fp16)
    agg_kernel<<<M, 128>>>((const __half*)p_hq, b1, (__half*)p_aq);
    // launch 5: layer-2 GEMM (fp16 out)
    gemm_mma<<<ggrid, 512, GEMM_SMEM>>>((const __half*)p_aq, (const __half*)p_w2,
                                        (__half*)p_hq, M);
    // launch 6: agg2 (fp16 gather -> fp16)
    agg_kernel<<<M, 128>>>((const __half*)p_hq, b2, (__half*)p_aq);
    // launch 7: logits (smem-staged)
    final_gemm<<<(M + 15) / 16, dim3(16, 16)>>>((const __half*)p_aq, Wl, bl, out, M);
}